// round 2
// baseline (speedup 1.0000x reference)
#include <cuda_runtime.h>
#include <math.h>

#define HP 138
#define WP 138
#define NB 8
#define ND 200
#define NK 32
#define H0 550
#define W0 550
#define NC 3

// ---------------- scratch (device globals; no allocations allowed) ----------
__device__ float g_gx [NB * ND * WP];   // exp(-dx^2/(2 sx^2))               [b,n,w]
__device__ float g_gyc[NB * ND * HP];   // exp(-dy^2/(2 sy^2)) * conf[b,n]   [b,n,h]
__device__ float g_fc [NB * HP * WP];   // final_conf                        [b,h,w]
__device__ float g_partial[2048];       // per-block partial sums of kernel C

// ---------------- Kernel A: separable gaussian profiles ---------------------
__global__ void gauss_kernel(const float* __restrict__ loc,
                             const float* __restrict__ conf) {
    int bn = blockIdx.x;            // b*ND + n
    int t  = threadIdx.x;
    if (t >= WP) return;            // HP == WP == 138
    float cx = loc[bn * 4 + 0];
    float cy = loc[bn * 4 + 1];
    float w  = loc[bn * 4 + 2];
    float h  = loc[bn * 4 + 3];
    float sx = fmaxf(w, 1e-3f);
    float sy = fmaxf(h, 1e-3f);
    float c  = conf[bn];

    float xs = (t + 0.5f) * (1.0f / (float)WP);
    float dx = xs - cx;
    g_gx[bn * WP + t] = __expf(-dx * dx * __fdividef(0.5f, sx * sx));

    float ys = (t + 0.5f) * (1.0f / (float)HP);
    float dy = ys - cy;
    g_gyc[bn * HP + t] = __expf(-dy * dy * __fdividef(0.5f, sy * sy)) * c;
}

// ---------------- Kernel B: fused lincomb + sigmoid + moment reduction ------
// One thread = one proto pixel (h,w). Block = 16x16 pixel tile of one batch.
// mask[b] (200x32 f32 = 25.6KB) staged in SMEM, read as broadcast float4.
// gx tile (200x16 = 12.8KB) staged in SMEM. gyc read via L1 (16 distinct rows).
__global__ __launch_bounds__(256)
void assemble_kernel(const float* __restrict__ mask,
                     const float* __restrict__ proto) {
    __shared__ float mask_s[ND * NK];   // 25600 B
    __shared__ float gx_s[ND * 16];     // 12800 B

    int b   = blockIdx.z;
    int w0  = blockIdx.x * 16;
    int h0  = blockIdx.y * 16;
    int tid = threadIdx.x;

    // stage mask[b]
    {
        const float4* msrc = (const float4*)(mask + (size_t)b * ND * NK);
        float4* mdst = (float4*)mask_s;
        #pragma unroll
        for (int i = tid; i < ND * NK / 4; i += 256) mdst[i] = msrc[i];
    }
    // stage gx tile
    for (int i = tid; i < ND * 16; i += 256) {
        int n = i >> 4, ww = i & 15;
        int gw = w0 + ww;
        gx_s[i] = (gw < WP) ? g_gx[(b * ND + n) * WP + gw] : 0.0f;
    }
    __syncthreads();

    int tx = tid & 15, ty = tid >> 4;
    int h = h0 + ty, w = w0 + tx;
    bool act = (h < HP) && (w < WP);
    int hh = act ? h : 0, wwc = act ? w : 0;

    // proto row -> registers (32 floats)
    float4 p[8];
    {
        const float4* psrc = (const float4*)(proto +
            ((size_t)(b * HP + hh) * WP + wwc) * NK);
        #pragma unroll
        for (int i = 0; i < 8; i++) p[i] = psrc[i];
    }

    const float4* mp  = (const float4*)mask_s;
    const float*  gxp = gx_s + tx;
    const float*  gyp = g_gyc + (size_t)b * ND * HP + hh;

    float s1 = 0.0f, s2 = 0.0f;
    #pragma unroll 2
    for (int n = 0; n < ND; n++) {
        float d0 = 0.f, d1 = 0.f, d2 = 0.f, d3 = 0.f;
        #pragma unroll
        for (int i = 0; i < 8; i += 4) {
            float4 m0 = mp[i + 0], m1 = mp[i + 1], m2 = mp[i + 2], m3 = mp[i + 3];
            d0 = fmaf(p[i+0].x, m0.x, d0); d0 = fmaf(p[i+0].y, m0.y, d0);
            d0 = fmaf(p[i+0].z, m0.z, d0); d0 = fmaf(p[i+0].w, m0.w, d0);
            d1 = fmaf(p[i+1].x, m1.x, d1); d1 = fmaf(p[i+1].y, m1.y, d1);
            d1 = fmaf(p[i+1].z, m1.z, d1); d1 = fmaf(p[i+1].w, m1.w, d1);
            d2 = fmaf(p[i+2].x, m2.x, d2); d2 = fmaf(p[i+2].y, m2.y, d2);
            d2 = fmaf(p[i+2].z, m2.z, d2); d2 = fmaf(p[i+2].w, m2.w, d2);
            d3 = fmaf(p[i+3].x, m3.x, d3); d3 = fmaf(p[i+3].y, m3.y, d3);
            d3 = fmaf(p[i+3].z, m3.z, d3); d3 = fmaf(p[i+3].w, m3.w, d3);
        }
        float d = (d0 + d1) + (d2 + d3);
        float a = __fdividef(1.0f, 1.0f + __expf(-d));   // sigmoid
        float mc = a * gxp[n * 16] * __ldg(gyp + n * HP);
        s1 += mc;
        s2 = fmaf(mc, mc, s2);
        mp += 8;
    }

    if (act) {
        float fc = 1.0f - __fdividef(s2, s1 + 1e-6f);
        if (isnan(fc)) fc = 0.0f;
        g_fc[(size_t)(b * HP + h) * WP + w] = fc;
    }
}

// ---------------- Kernel C: bilinear 138->550, weighted variance ------------
__global__ __launch_bounds__(256)
void finalize_kernel(const float* __restrict__ orig) {
    int p = blockIdx.x * 256 + threadIdx.x;
    float val = 0.0f;
    if (p < H0 * W0) {
        int i = p / W0, j = p % W0;
        const float scale = (float)HP / (float)H0;   // half-pixel centers
        float sy = (i + 0.5f) * scale - 0.5f;
        float sx = (j + 0.5f) * scale - 0.5f;
        float fy0 = floorf(sy), fx0 = floorf(sx);
        float fy = sy - fy0,   fx = sx - fx0;
        int y0 = (int)fy0,     x0 = (int)fx0;
        int y0c = min(max(y0, 0), HP - 1);
        int y1c = min(max(y0 + 1, 0), HP - 1);
        int x0c = min(max(x0, 0), WP - 1);
        int x1c = min(max(x0 + 1, 0), WP - 1);

        float r[NB];
        float total = 0.0f;
        #pragma unroll
        for (int b = 0; b < NB; b++) {
            const float* f = g_fc + (size_t)b * HP * WP;
            float v00 = __ldg(f + y0c * WP + x0c);
            float v01 = __ldg(f + y0c * WP + x1c);
            float v10 = __ldg(f + y1c * WP + x0c);
            float v11 = __ldg(f + y1c * WP + x1c);
            float v0 = v00 + (v01 - v00) * fx;
            float v1 = v10 + (v11 - v10) * fx;
            r[b] = v0 + (v1 - v0) * fy;
            total += r[b];
        }
        float inv_t  = __fdividef(1.0f, total);          // mean div (no eps, as ref)
        float inv_te = __fdividef(1.0f, total + 1e-6f);  // var div (+eps, as ref)

        #pragma unroll
        for (int c = 0; c < NC; c++) {
            float o[NB];
            float s = 0.0f;
            #pragma unroll
            for (int b = 0; b < NB; b++) {
                o[b] = __ldg(orig + ((size_t)(b * NC + c)) * (H0 * W0) + p);
                s = fmaf(o[b], r[b], s);
            }
            float wm = s * inv_t;
            float acc = 0.0f;
            #pragma unroll
            for (int b = 0; b < NB; b++) {
                float d = o[b] - wm;
                acc = fmaf(d * d, r[b], acc);
            }
            val += acc * inv_te;
        }
        val *= (float)NB / (float)NK;   // * B / K
    }

    __shared__ float red[256];
    red[threadIdx.x] = val;
    __syncthreads();
    #pragma unroll
    for (int s = 128; s > 0; s >>= 1) {
        if (threadIdx.x < s) red[threadIdx.x] += red[threadIdx.x + s];
        __syncthreads();
    }
    if (threadIdx.x == 0) g_partial[blockIdx.x] = red[0];
}

// ---------------- Kernel D: deterministic final reduce -----------------------
__global__ void reduce_kernel(float* __restrict__ out, int nblocks) {
    __shared__ float red[1024];
    float s = 0.0f;
    for (int i = threadIdx.x; i < nblocks; i += 1024) s += g_partial[i];
    red[threadIdx.x] = s;
    __syncthreads();
    #pragma unroll
    for (int st = 512; st > 0; st >>= 1) {
        if (threadIdx.x < st) red[threadIdx.x] += red[threadIdx.x + st];
        __syncthreads();
    }
    if (threadIdx.x == 0) out[0] = red[0];
}

// ---------------- launch ------------------------------------------------------
extern "C" void kernel_launch(void* const* d_in, const int* in_sizes, int n_in,
                              void* d_out, int out_size) {
    const float* original = (const float*)d_in[0];  // [8,3,550,550]
    const float* loc      = (const float*)d_in[1];  // [8,200,4]
    const float* maskp    = (const float*)d_in[2];  // [8,200,32]
    const float* confp    = (const float*)d_in[3];  // [8,200]
    const float* proto    = (const float*)d_in[4];  // [8,138,138,32]
    float* out = (float*)d_out;

    gauss_kernel<<<NB * ND, 160>>>(loc, confp);

    dim3 gB((WP + 15) / 16, (HP + 15) / 16, NB);
    assemble_kernel<<<gB, 256>>>(maskp, proto);

    int nb = (H0 * W0 + 255) / 256;   // 1182
    finalize_kernel<<<nb, 256>>>(original);

    reduce_kernel<<<1, 1024>>>(out, nb);
}